// round 5
// baseline (speedup 1.0000x reference)
#include <cuda_runtime.h>
#include <cstdint>

// Problem constants (fixed shapes from setup_inputs):
//   log_probs: (128, 64) float32
//   ref:       (256, 128) int32 (JAX x64 disabled downcasts int64 -> int32!)
//   hyp:       (256, 128, 64) int32
#define NBATCH 128
#define NSAMP  64
#define NSEQ   (NBATCH * NSAMP)   // 8192
#define RLEN   256
#define HLEN   256
#define SYMS   1024               // tokens in [0,1000); padded to pow2 for addressing

// Scratch (static __device__ arrays: allocation-free per harness rules)
__device__ unsigned long long d_Peq[(size_t)NBATCH * SYMS * 4];  // 4 MB bitmask table
__device__ int    d_ref_len[NBATCH];
__device__ float  d_er[NSEQ];
__device__ double d_partial[NBATCH];

// ---------------------------------------------------------------------------
// Kernel 1: zero the Peq table (must happen every call; graph replays)
// ---------------------------------------------------------------------------
__global__ void zero_peq_kernel() {
    size_t i = (size_t)blockIdx.x * blockDim.x + threadIdx.x;  // 2048*256 = 524288 words
    d_Peq[i] = 0ull;
}

// ---------------------------------------------------------------------------
// Kernel 2: per-batch ref length + Peq bitmask build.
// Block b handles ref column b; thread j handles ref position j.
// ---------------------------------------------------------------------------
__global__ void build_peq_kernel(const int* __restrict__ ref) {
    int b = blockIdx.x;
    int j = threadIdx.x;  // 0..255
    __shared__ int minEos;
    if (j == 0) minEos = RLEN;
    __syncthreads();
    int tok = ref[(size_t)j * NBATCH + b];
    if (tok == 0) atomicMin(&minEos, j);
    __syncthreads();
    int len = (minEos < RLEN) ? (minEos + 1) : RLEN;  // INCLUDE_EOS
    if (j == 0) d_ref_len[b] = len;
    if (j < len) {
        int t = tok & (SYMS - 1);
        atomicOr(&d_Peq[(((size_t)b * SYMS + t) << 2) + (j >> 6)], 1ull << (j & 63));
    }
}

// ---------------------------------------------------------------------------
// Kernel 3: Myers bit-parallel Levenshtein (4x64-bit blocks, edlib carry form).
// One thread per sequence. Block b = batch row b (its 32KB Peq slice is L1-hot).
// Software-pipelined: next token + Peq words load before current ALU chain.
// ---------------------------------------------------------------------------
__global__ void __launch_bounds__(NSAMP, 1) myers_kernel(const int* __restrict__ hyp) {
    int b = blockIdx.x;
    int s = threadIdx.x;
    int n = b * NSAMP + s;

    int m    = d_ref_len[b];         // uniform within block
    int bsel = (m - 1) >> 6;         // word containing the score row
    int pm   = (m - 1) & 63;         // bit within that word

    const unsigned long long* __restrict__ peq = d_Peq + ((size_t)b << 12);  // b*1024*4

    unsigned long long Pv[4] = {~0ull, ~0ull, ~0ull, ~0ull};
    unsigned long long Mv[4] = {0ull, 0ull, 0ull, 0ull};
    int score = m;

    // pipeline prologue: token 0
    int c = hyp[n] & (SYMS - 1);
    const unsigned long long* pe0 = peq + ((size_t)c << 2);
    unsigned long long E[4] = {pe0[0], pe0[1], pe0[2], pe0[3]};

    for (int h = 0; h < HLEN; ++h) {
        // prefetch next step's token + Eq words (hides L1/L2 latency under chain)
        int cn = 0;
        if (h + 1 < HLEN) cn = hyp[(size_t)(h + 1) * NSEQ + n] & (SYMS - 1);
        const unsigned long long* pen = peq + ((size_t)cn << 2);
        unsigned long long En0 = pen[0], En1 = pen[1], En2 = pen[2], En3 = pen[3];

        unsigned long long phin = 1ull;   // D[i][0] = i boundary
        unsigned long long mhin = 0ull;
        #pragma unroll
        for (int w = 0; w < 4; ++w) {
            unsigned long long Eq = E[w];
            unsigned long long Xv = Eq | Mv[w];
            Eq |= mhin;
            unsigned long long Xh = (((Eq & Pv[w]) + Pv[w]) ^ Pv[w]) | Eq;
            unsigned long long Ph = Mv[w] | ~(Xh | Pv[w]);
            unsigned long long Mh = Pv[w] & Xh;
            if (w == bsel)  // uniform predicate per block
                score += (int)((Ph >> pm) & 1ull) - (int)((Mh >> pm) & 1ull);
            unsigned long long phout = Ph >> 63;
            unsigned long long mhout = Mh >> 63;
            Ph = (Ph << 1) | phin;
            Mh = (Mh << 1) | mhin;
            Pv[w] = Mh | ~(Xv | Ph);
            Mv[w] = Ph & Xv;
            phin = phout;
            mhin = mhout;
        }

        if (c == 0) break;  // hyp ended at this (EOS-inclusive) step
        c = cn;
        E[0] = En0; E[1] = En1; E[2] = En2; E[3] = En3;
    }

    d_er[n] = (float)score / (float)m;  // normalized error rate
}

// ---------------------------------------------------------------------------
// Kernel 4: per-batch softmax-weighted centered error (one warp per batch row)
//   partial[b] = sum_s (er_s - mean_s er) * softmax(lp)_s
//              = (sum er*e)/(sum e) - (sum er)/64
// ---------------------------------------------------------------------------
__global__ void reduce_batch_kernel(const float* __restrict__ logp) {
    int b = blockIdx.x, lane = threadIdx.x;  // 32 lanes, 2 samples each
    int base = b * NSAMP;
    float er0 = d_er[base + lane],      er1 = d_er[base + 32 + lane];
    float lp0 = logp[base + lane],      lp1 = logp[base + 32 + lane];

    float mx = fmaxf(lp0, lp1);
    #pragma unroll
    for (int o = 16; o; o >>= 1) mx = fmaxf(mx, __shfl_xor_sync(0xffffffffu, mx, o));

    float e0 = expf(lp0 - mx), e1 = expf(lp1 - mx);
    float se  = e0 + e1;
    float ser = er0 + er1;
    float sep = er0 * e0 + er1 * e1;
    #pragma unroll
    for (int o = 16; o; o >>= 1) {
        se  += __shfl_xor_sync(0xffffffffu, se,  o);
        ser += __shfl_xor_sync(0xffffffffu, ser, o);
        sep += __shfl_xor_sync(0xffffffffu, sep, o);
    }
    if (lane == 0)
        d_partial[b] = (double)sep / (double)se - (double)ser / 64.0;
}

// ---------------------------------------------------------------------------
// Kernel 5: final mean over all (batch, sample): loss = sum(partial)/8192
// ---------------------------------------------------------------------------
__global__ void final_reduce_kernel(float* __restrict__ out) {
    __shared__ double sh[NBATCH];
    int t = threadIdx.x;
    sh[t] = d_partial[t];
    __syncthreads();
    #pragma unroll
    for (int o = 64; o; o >>= 1) {
        if (t < o) sh[t] += sh[t + o];
        __syncthreads();
    }
    if (t == 0) out[0] = (float)(sh[0] / (double)NSEQ);
}

// ---------------------------------------------------------------------------
extern "C" void kernel_launch(void* const* d_in, const int* in_sizes, int n_in,
                              void* d_out, int out_size) {
    const float* logp = (const float*)d_in[0];  // (128,64) f32
    const int*   ref  = (const int*)d_in[1];    // (256,128) i32
    const int*   hyp  = (const int*)d_in[2];    // (256,128,64) i32
    float* out = (float*)d_out;

    zero_peq_kernel<<<2048, 256>>>();            // 524288 words of Peq
    build_peq_kernel<<<NBATCH, RLEN>>>(ref);
    myers_kernel<<<NBATCH, NSAMP>>>(hyp);
    reduce_batch_kernel<<<NBATCH, 32>>>(logp);
    final_reduce_kernel<<<1, NBATCH>>>(out);
}

// round 6
// speedup vs baseline: 1.8902x; 1.8902x over previous
#include <cuda_runtime.h>
#include <cstdint>

// Shapes (fixed):
//   log_probs: (128, 64) float32
//   ref:       (256, 128) int32
//   hyp:       (256, 128, 64) int32
#define NBATCH 128
#define NSAMP  64
#define NSEQ   (NBATCH * NSAMP)   // 8192
#define RLEN   256
#define HLEN   256
#define SYMS   1024               // tokens in [0,1000); pow2 for addressing
#define TPD    6                  // token prefetch depth (covers DRAM latency)

typedef unsigned long long ull;

__device__ double d_partial[NBATCH];

// ---------------------------------------------------------------------------
// Fused kernel: per-block (= per batch row b)
//   1. build Peq bitmask table for ref column b in SMEM (32 KB)
//   2. 64 threads run Myers bit-parallel Levenshtein (4x64-bit blocks),
//      hyp tokens prefetched 6 steps deep, Peq gathered from SMEM 1 step ahead
//   3. block-level softmax-weighted centered reduction -> d_partial[b]
// ---------------------------------------------------------------------------
__global__ void __launch_bounds__(NSAMP, 1)
myers_fused_kernel(const int* __restrict__ hyp,
                   const int* __restrict__ ref,
                   const float* __restrict__ logp) {
    __shared__ ull   sPeq[SYMS * 4];   // 32 KB
    __shared__ int   sMinEos;
    __shared__ float sEr[NSAMP];

    const int b = blockIdx.x;
    const int s = threadIdx.x;           // 0..63
    const int n = b * NSAMP + s;

    // ---- build Peq in SMEM ----
    if (s == 0) sMinEos = RLEN;
    #pragma unroll
    for (int i = s; i < SYMS * 4; i += NSAMP) sPeq[i] = 0ull;
    __syncthreads();

    int rtok[RLEN / NSAMP];  // 4 ref tokens per thread
    #pragma unroll
    for (int k = 0; k < RLEN / NSAMP; ++k) {
        int j = s + k * NSAMP;
        rtok[k] = ref[(size_t)j * NBATCH + b];
        if (rtok[k] == 0) atomicMin(&sMinEos, j);
    }
    __syncthreads();
    const int m = (sMinEos < RLEN) ? (sMinEos + 1) : RLEN;  // INCLUDE_EOS
    #pragma unroll
    for (int k = 0; k < RLEN / NSAMP; ++k) {
        int j = s + k * NSAMP;
        if (j < m)
            atomicOr(&sPeq[((rtok[k] & (SYMS - 1)) << 2) + (j >> 6)], 1ull << (j & 63));
    }
    __syncthreads();

    // ---- Myers DP ----
    const int bsel = (m - 1) >> 6;
    const int pm   = (m - 1) & 63;

    ull Pv0 = ~0ull, Pv1 = ~0ull, Pv2 = ~0ull, Pv3 = ~0ull;
    ull Mv0 = 0ull,  Mv1 = 0ull,  Mv2 = 0ull,  Mv3 = 0ull;
    int score = m;

    // token ring, depth TPD (HLEN=256 > TPD so no guards needed in prologue)
    int t0 = hyp[n] & (SYMS - 1);
    int t1 = hyp[(size_t)1 * NSEQ + n] & (SYMS - 1);
    int t2 = hyp[(size_t)2 * NSEQ + n] & (SYMS - 1);
    int t3 = hyp[(size_t)3 * NSEQ + n] & (SYMS - 1);
    int t4 = hyp[(size_t)4 * NSEQ + n] & (SYMS - 1);
    int t5 = hyp[(size_t)5 * NSEQ + n] & (SYMS - 1);

    const ull* pe = sPeq + (t0 << 2);
    ull E0 = pe[0], E1 = pe[1], E2 = pe[2], E3 = pe[3];

    for (int h = 0; h < HLEN; ++h) {
        // issue hyp load TPD steps ahead (address-independent, fully hidden)
        int tnew = 0;
        if (h + TPD < HLEN) tnew = hyp[(size_t)(h + TPD) * NSEQ + n];

        // SMEM gather for next step's Eq (29-cyc LDS, hidden under ALU chain)
        const ull* pn = sPeq + (t1 << 2);
        ull N0 = pn[0], N1 = pn[1], N2 = pn[2], N3 = pn[3];

        ull phin = 1ull, mhin = 0ull;
        {   // word 0
            ull Eq = E0;
            ull Xv = Eq | Mv0;  Eq |= mhin;
            ull Xh = (((Eq & Pv0) + Pv0) ^ Pv0) | Eq;
            ull Ph = Mv0 | ~(Xh | Pv0);
            ull Mh = Pv0 & Xh;
            if (bsel == 0) score += (int)((Ph >> pm) & 1ull) - (int)((Mh >> pm) & 1ull);
            ull po = Ph >> 63, mo = Mh >> 63;
            Ph = (Ph << 1) | phin;  Mh = (Mh << 1) | mhin;
            Pv0 = Mh | ~(Xv | Ph);  Mv0 = Ph & Xv;
            phin = po; mhin = mo;
        }
        {   // word 1
            ull Eq = E1;
            ull Xv = Eq | Mv1;  Eq |= mhin;
            ull Xh = (((Eq & Pv1) + Pv1) ^ Pv1) | Eq;
            ull Ph = Mv1 | ~(Xh | Pv1);
            ull Mh = Pv1 & Xh;
            if (bsel == 1) score += (int)((Ph >> pm) & 1ull) - (int)((Mh >> pm) & 1ull);
            ull po = Ph >> 63, mo = Mh >> 63;
            Ph = (Ph << 1) | phin;  Mh = (Mh << 1) | mhin;
            Pv1 = Mh | ~(Xv | Ph);  Mv1 = Ph & Xv;
            phin = po; mhin = mo;
        }
        {   // word 2
            ull Eq = E2;
            ull Xv = Eq | Mv2;  Eq |= mhin;
            ull Xh = (((Eq & Pv2) + Pv2) ^ Pv2) | Eq;
            ull Ph = Mv2 | ~(Xh | Pv2);
            ull Mh = Pv2 & Xh;
            if (bsel == 2) score += (int)((Ph >> pm) & 1ull) - (int)((Mh >> pm) & 1ull);
            ull po = Ph >> 63, mo = Mh >> 63;
            Ph = (Ph << 1) | phin;  Mh = (Mh << 1) | mhin;
            Pv2 = Mh | ~(Xv | Ph);  Mv2 = Ph & Xv;
            phin = po; mhin = mo;
        }
        {   // word 3
            ull Eq = E3;
            ull Xv = Eq | Mv3;  Eq |= mhin;
            ull Xh = (((Eq & Pv3) + Pv3) ^ Pv3) | Eq;
            ull Ph = Mv3 | ~(Xh | Pv3);
            ull Mh = Pv3 & Xh;
            if (bsel == 3) score += (int)((Ph >> pm) & 1ull) - (int)((Mh >> pm) & 1ull);
            ull po = Ph >> 63, mo = Mh >> 63;
            Ph = (Ph << 1) | phin;  Mh = (Mh << 1) | mhin;
            Pv3 = Mh | ~(Xv | Ph);  Mv3 = Ph & Xv;
            phin = po; mhin = mo;
        }

        if (t0 == 0) break;  // hyp ended (EOS-inclusive step done)

        // rotate ring + install prefetched Eq
        t0 = t1; t1 = t2; t2 = t3; t3 = t4; t4 = t5; t5 = tnew & (SYMS - 1);
        E0 = N0; E1 = N1; E2 = N2; E3 = N3;
    }

    sEr[s] = (float)score / (float)m;
    __syncthreads();

    // ---- per-batch reduction (warp 0): partial = sum er*p - mean(er) ----
    if (s < 32) {
        int lane = s, base = b * NSAMP;
        float er0 = sEr[lane],            er1 = sEr[lane + 32];
        float lp0 = logp[base + lane],    lp1 = logp[base + 32 + lane];

        float mx = fmaxf(lp0, lp1);
        #pragma unroll
        for (int o = 16; o; o >>= 1) mx = fmaxf(mx, __shfl_xor_sync(0xffffffffu, mx, o));

        float e0 = expf(lp0 - mx), e1 = expf(lp1 - mx);
        float se  = e0 + e1;
        float ser = er0 + er1;
        float sep = er0 * e0 + er1 * e1;
        #pragma unroll
        for (int o = 16; o; o >>= 1) {
            se  += __shfl_xor_sync(0xffffffffu, se,  o);
            ser += __shfl_xor_sync(0xffffffffu, ser, o);
            sep += __shfl_xor_sync(0xffffffffu, sep, o);
        }
        if (lane == 0)
            d_partial[b] = (double)sep / (double)se - (double)ser / 64.0;
    }
}

// ---------------------------------------------------------------------------
// Final mean: loss = sum_b partial[b] / 8192
// ---------------------------------------------------------------------------
__global__ void final_reduce_kernel(float* __restrict__ out) {
    __shared__ double sh[NBATCH];
    int t = threadIdx.x;
    sh[t] = d_partial[t];
    __syncthreads();
    #pragma unroll
    for (int o = 64; o; o >>= 1) {
        if (t < o) sh[t] += sh[t + o];
        __syncthreads();
    }
    if (t == 0) out[0] = (float)(sh[0] / (double)NSEQ);
}

// ---------------------------------------------------------------------------
extern "C" void kernel_launch(void* const* d_in, const int* in_sizes, int n_in,
                              void* d_out, int out_size) {
    const float* logp = (const float*)d_in[0];  // (128,64) f32
    const int*   ref  = (const int*)d_in[1];    // (256,128) i32
    const int*   hyp  = (const int*)d_in[2];    // (256,128,64) i32
    float* out = (float*)d_out;

    myers_fused_kernel<<<NBATCH, NSAMP>>>(hyp, ref, logp);
    final_reduce_kernel<<<1, NBATCH>>>(out);
}